// round 9
// baseline (speedup 1.0000x reference)
#include <cuda_runtime.h>
#include <cuda_fp16.h>
#include <math_constants.h>

#define NB 16
#define NC 32
#define NO 32
#define HH 256
#define WW 256
#define WB 129

// Frequency-domain scratch in fp16 (half2 = one complex), layout [img][wb][h];
// h is PERMUTED (position k2*32+lane <-> freq 8*br5(lane)+k2).
__device__ __half2 g_Xf[(size_t)NB * NC * WB * HH];
__device__ __half2 g_Kf[(size_t)NO * NC * WB * HH];
__device__ __half2 g_Of[(size_t)NB * NO * WB * HH];

// ---------------------------------------------------------------------------
// Packed complex: one fp32 (re, im) pair in a 64-bit register pair (f32x2).
// ---------------------------------------------------------------------------
typedef unsigned long long cplx;

__device__ __forceinline__ cplx cpk(float x, float y) {
    cplx r; asm("mov.b64 %0, {%1, %2};" : "=l"(r) : "f"(x), "f"(y)); return r;
}
__device__ __forceinline__ float2 cup(cplx a) {
    float2 r; asm("mov.b64 {%0, %1}, %2;" : "=f"(r.x), "=f"(r.y) : "l"(a)); return r;
}
__device__ __forceinline__ cplx cadd2(cplx a, cplx b) {
    cplx r; asm("add.rn.f32x2 %0, %1, %2;" : "=l"(r) : "l"(a), "l"(b)); return r;
}
__device__ __forceinline__ cplx cmul2(cplx a, cplx b) {
    cplx r; asm("mul.rn.f32x2 %0, %1, %2;" : "=l"(r) : "l"(a), "l"(b)); return r;
}
__device__ __forceinline__ cplx cfma2(cplx a, cplx b, cplx c) {
    cplx r; asm("fma.rn.f32x2 %0, %1, %2, %3;" : "=l"(r) : "l"(a), "l"(b), "l"(c)); return r;
}
__device__ __forceinline__ cplx cmulw(cplx a, float2 w) {
    float2 t = cup(a);
    return cfma2(cpk(t.y, t.x), cpk(-w.y, w.y), cmul2(a, cpk(w.x, w.x)));
}
template <int DIR>
__device__ __forceinline__ cplx mulJp(cplx a) {
    float2 t = cup(a);
    return (DIR > 0) ? cpk(t.y, -t.x) : cpk(-t.y, t.x);
}
__device__ __forceinline__ float2 cmulf(float2 a, float2 b) {
    return make_float2(fmaf(a.x, b.x, -a.y * b.y), fmaf(a.x, b.y, a.y * b.x));
}
__device__ __forceinline__ float2 h2f(__half2 h) { return __half22float2(h); }
__device__ __forceinline__ __half2 f2h(float2 f) { return __floats2half2_rn(f.x, f.y); }

// ---------------------------------------------------------------------------
// FFT8 over register slots, e^{-i} for DIR=+1
// ---------------------------------------------------------------------------
template <int DIR>
__device__ __forceinline__ void fft8_slots(cplx v[8]) {
    const cplx N1 = cpk(-1.0f, -1.0f);
    const float ds = (DIR > 0) ? -1.0f : 1.0f;
    const float S = 0.70710678118654752f;
    cplx b0 = cadd2(v[0], v[4]), b1 = cfma2(v[4], N1, v[0]);
    cplx b2 = cadd2(v[2], v[6]), b3 = cfma2(v[6], N1, v[2]);
    cplx b4 = cadd2(v[1], v[5]), b5 = cfma2(v[5], N1, v[1]);
    cplx b6 = cadd2(v[3], v[7]), b7 = cfma2(v[7], N1, v[3]);
    cplx t  = mulJp<DIR>(b3);
    cplx c0 = cadd2(b0, b2), c2 = cfma2(b2, N1, b0);
    cplx c1 = cadd2(b1, t),  c3 = cfma2(t, N1, b1);
    t = mulJp<DIR>(b7);
    cplx c4 = cadd2(b4, b6), c6 = cfma2(b6, N1, b4);
    cplx c5 = cadd2(b5, t),  c7 = cfma2(t, N1, b5);
    const float2 W81 = make_float2(S, ds * S);
    const float2 W83 = make_float2(-S, ds * S);
    v[0] = cadd2(c0, c4); v[4] = cfma2(c4, N1, c0);
    t = cmulw(c5, W81);   v[1] = cadd2(c1, t); v[5] = cfma2(t, N1, c1);
    t = mulJp<DIR>(c6);   v[2] = cadd2(c2, t); v[6] = cfma2(t, N1, c2);
    t = cmulw(c7, W83);   v[3] = cadd2(c3, t); v[7] = cfma2(t, N1, c3);
}

// Forward register/shuffle FFT-256. Input v[j]=x[lane+32*j]. Output: lane
// holds X[8*br5(lane)+k2] in v[k2].
template <int DIR>
__device__ __forceinline__ void fft256(cplx v[8], int lane) {
    const float ds = (DIR > 0) ? -1.0f : 1.0f;
    fft8_slots<DIR>(v);

    float ang = ds * CUDART_PI_F * (float)lane * (1.0f / 128.0f);
    float2 w1; __sincosf(ang, &w1.y, &w1.x);
    float2 w2 = cmulf(w1, w1);
    float2 w3 = cmulf(w2, w1);
    float2 w4 = cmulf(w2, w2);
    float2 w5 = cmulf(w4, w1);
    float2 w6 = cmulf(w3, w3);
    float2 w7 = cmulf(w4, w3);
    v[1] = cmulw(v[1], w1); v[2] = cmulw(v[2], w2); v[3] = cmulw(v[3], w3);
    v[4] = cmulw(v[4], w4); v[5] = cmulw(v[5], w5); v[6] = cmulw(v[6], w6);
    v[7] = cmulw(v[7], w7);

#pragma unroll
    for (int m = 16; m >= 1; m >>= 1) {
        bool up = (lane & m) != 0;
        float s = up ? -1.0f : 1.0f;
        cplx s2 = cpk(s, s);
        cplx wxx, wmy;
        if (m > 1) {
            float a2 = ds * CUDART_PI_F * (float)(lane & (m - 1)) / (float)m;
            float2 w; __sincosf(a2, &w.y, &w.x);
            float2 wo = up ? w : make_float2(1.0f, 0.0f);
            wxx = cpk(wo.x, wo.x);
            wmy = cpk(-wo.y, wo.y);
        }
#pragma unroll
        for (int k = 0; k < 8; k++) {
            float2 t = cup(v[k]);
            float ox = __shfl_xor_sync(0xffffffffu, t.x, m);
            float oy = __shfl_xor_sync(0xffffffffu, t.y, m);
            cplx tt = cfma2(v[k], s2, cpk(ox, oy));
            if (m > 1) {
                float2 u = cup(tt);
                v[k] = cfma2(cpk(u.y, u.x), wmy, cmul2(tt, wxx));
            } else {
                v[k] = tt;
            }
        }
    }
}

// Adjoint (unnormalized inverse) of fft256<1>: permuted in, natural out.
__device__ __forceinline__ void ifft256_adj(cplx v[8], int lane) {
#pragma unroll
    for (int m = 1; m <= 16; m <<= 1) {
        bool up = (lane & m) != 0;
        float s = up ? -1.0f : 1.0f;
        cplx s2 = cpk(s, s);
        if (m > 1) {
            float a2 = CUDART_PI_F * (float)(lane & (m - 1)) / (float)m;
            float2 w; __sincosf(a2, &w.y, &w.x);
            float2 wo = up ? w : make_float2(1.0f, 0.0f);
            cplx wxx = cpk(wo.x, wo.x);
            cplx wmy = cpk(-wo.y, wo.y);
#pragma unroll
            for (int k = 0; k < 8; k++) {
                float2 u = cup(v[k]);
                v[k] = cfma2(cpk(u.y, u.x), wmy, cmul2(v[k], wxx));
            }
        }
#pragma unroll
        for (int k = 0; k < 8; k++) {
            float2 t = cup(v[k]);
            float ox = __shfl_xor_sync(0xffffffffu, t.x, m);
            float oy = __shfl_xor_sync(0xffffffffu, t.y, m);
            v[k] = cfma2(v[k], s2, cpk(ox, oy));
        }
    }
    float ang = CUDART_PI_F * (float)lane * (1.0f / 128.0f);
    float2 w1; __sincosf(ang, &w1.y, &w1.x);
    float2 w2 = cmulf(w1, w1);
    float2 w3 = cmulf(w2, w1);
    float2 w4 = cmulf(w2, w2);
    float2 w5 = cmulf(w4, w1);
    float2 w6 = cmulf(w3, w3);
    float2 w7 = cmulf(w4, w3);
    v[1] = cmulw(v[1], w1); v[2] = cmulw(v[2], w2); v[3] = cmulw(v[3], w3);
    v[4] = cmulw(v[4], w4); v[5] = cmulw(v[5], w5); v[6] = cmulw(v[6], w6);
    v[7] = cmulw(v[7], w7);

    fft8_slots<-1>(v);
}

// ---------------------------------------------------------------------------
// Fused forward 2D rFFT: one CTA per image.
// Phase 1: 128 packed-pair row FFTs -> smem Zt[256][128] (XOR-swizzled).
// Phase 2: Hermitian unpack + column FFT per wb -> gmem (permuted h, coalesced)
// ---------------------------------------------------------------------------
__global__ void __launch_bounds__(1024)
fwd_kernel(const float* __restrict__ in, __half2* __restrict__ outF) {
    extern __shared__ __half2 Zt[];   // 256 * 128, addr = k*128 + (p ^ br5row)
    int tid = threadIdx.x, lane = tid & 31, wrp = tid >> 5;
    size_t img = blockIdx.x;

    // Phase 1: packed row FFTs (rows 2p, 2p+1)
#pragma unroll
    for (int it = 0; it < 4; it++) {
        int pi = it * 32 + wrp;       // pair 0..127
        const float* pa = in + (img * HH + 2 * pi) * (size_t)WW;
        const float* pb = pa + WW;
        cplx v[8];
#pragma unroll
        for (int j = 0; j < 8; j++)
            v[j] = cpk(pa[lane + 32 * j], pb[lane + 32 * j]);

        fft256<1>(v, lane);

        int b = __brev((unsigned)lane) >> 27;
#pragma unroll
        for (int k2 = 0; k2 < 8; k2++)
            Zt[(8 * b + k2) * 128 + (pi ^ b)] = f2h(cup(v[k2]));
    }
    __syncthreads();

    // Phase 2: unpack + column FFT per wb
    for (int it = 0; it < 5; it++) {
        int wb = it * 32 + wrp;
        if (wb <= 128) {
            int wbm = (256 - wb) & 255;
            int sa = (wb >> 3) & 31, sb = (wbm >> 3) & 31;
            cplx v[8];
#pragma unroll
            for (int j = 0; j < 8; j++) {
                int h = lane + 32 * j, p = h >> 1;
                float2 Z  = h2f(Zt[wb  * 128 + (p ^ sa)]);
                float2 Zm = h2f(Zt[wbm * 128 + (p ^ sb)]);
                float2 r = (lane & 1)
                    ? make_float2(0.5f * (Z.y + Zm.y), 0.5f * (Zm.x - Z.x))
                    : make_float2(0.5f * (Z.x + Zm.x), 0.5f * (Z.y - Zm.y));
                v[j] = cpk(r.x, r.y);
            }
            fft256<1>(v, lane);
            __half2* po = outF + (img * WB + wb) * (size_t)HH;
#pragma unroll
            for (int k2 = 0; k2 < 8; k2++)
                po[k2 * 32 + lane] = f2h(cup(v[k2]));     // coalesced
        }
    }
}

// ---------------------------------------------------------------------------
// Fused inverse 2D rFFT: one CTA per output image.
// Phase 1: adjoint column FFT per wb (coalesced permuted load) -> smem
//          St[129][256] with (h ^ wb) swizzle, natural h.
// Phase 2: packed-pair inverse row FFTs + 1/(H*W) scale -> gmem fp32.
// ---------------------------------------------------------------------------
__global__ void __launch_bounds__(1024)
inv_kernel(const __half2* __restrict__ OF, float* __restrict__ out) {
    extern __shared__ __half2 St[];   // 129 * 256, addr = wb*256 + (h ^ (wb&31))
    int tid = threadIdx.x, lane = tid & 31, wrp = tid >> 5;
    size_t img = blockIdx.x;

    // Phase 1: inverse column FFTs
    for (int it = 0; it < 5; it++) {
        int wb = it * 32 + wrp;
        if (wb <= 128) {
            const __half2* p = OF + (img * WB + wb) * (size_t)HH;
            cplx v[8];
#pragma unroll
            for (int k2 = 0; k2 < 8; k2++) {
                float2 f = h2f(p[k2 * 32 + lane]);
                v[k2] = cpk(f.x, f.y);
            }
            ifft256_adj(v, lane);
            int sw = wb & 31;
#pragma unroll
            for (int j = 0; j < 8; j++)
                St[wb * 256 + ((lane + 32 * j) ^ sw)] = f2h(cup(v[j]));
        }
    }
    __syncthreads();

    // Phase 2: packed inverse row FFTs (rows 2p, 2p+1)
#pragma unroll
    for (int it = 0; it < 4; it++) {
        int pi = it * 32 + wrp;       // pair 0..127
        int r0 = 2 * pi, r1 = 2 * pi + 1;
        cplx v[8];
#pragma unroll
        for (int j = 0; j < 8; j++) {
            int k = lane + 32 * j;
            float2 r;
            if (k <= 128) {
                int sw = k & 31;
                float2 A  = h2f(St[k * 256 + (r0 ^ sw)]);
                float2 Bv = h2f(St[k * 256 + (r1 ^ sw)]);
                r = make_float2(A.x - Bv.y, A.y + Bv.x);
            } else {
                int km = 256 - k, sw = km & 31;
                float2 A  = h2f(St[km * 256 + (r0 ^ sw)]);
                float2 Bv = h2f(St[km * 256 + (r1 ^ sw)]);
                r = make_float2(A.x + Bv.y, Bv.x - A.y);
            }
            v[j] = cpk(r.x, r.y);
        }

        fft256<-1>(v, lane);

        const float sc = 1.0f / 65536.0f;
        int base = 8 * (__brev((unsigned)lane) >> 27);
        float* oa = out + (img * HH + r0) * (size_t)WW + base;
        float* ob = oa + WW;
        float4* oa4 = (float4*)oa; float4* ob4 = (float4*)ob;
        float2 f[8];
#pragma unroll
        for (int j = 0; j < 8; j++) f[j] = cup(v[j]);
#pragma unroll
        for (int qq = 0; qq < 2; qq++) {
            oa4[qq] = make_float4(f[4*qq].x * sc, f[4*qq+1].x * sc, f[4*qq+2].x * sc, f[4*qq+3].x * sc);
            ob4[qq] = make_float4(f[4*qq].y * sc, f[4*qq+1].y * sc, f[4*qq+2].y * sc, f[4*qq+3].y * sc);
        }
    }
}

// ---------------------------------------------------------------------------
// Per-bin channel contraction, 4b x 2o register tiling, fp32 smem (unchanged).
// ---------------------------------------------------------------------------
#define XSTR 18
#define KSTR 34
__global__ void __launch_bounds__(512, 2)
binconv_kernel(const __half2* __restrict__ Xf, const __half2* __restrict__ Kf,
               __half2* __restrict__ Of) {
    extern __shared__ float2 sm[];
    float2* Xs = sm;
    float2* Ks = sm + 32 * 8 * XSTR;

    int tid = threadIdx.x;
    int wb = blockIdx.y;
    int h0 = blockIdx.x * 8;
    int hl = tid & 7;
    int sub = tid >> 3;

#pragma unroll
    for (int i = 0; i < 8; i++) {
        int img = i * 64 + sub;           // b*32 + c
        Xs[((img & 31) * 8 + hl) * XSTR + (img >> 5)] =
            h2f(Xf[((size_t)img * WB + wb) * HH + h0 + hl]);
    }
#pragma unroll
    for (int i = 0; i < 16; i++) {
        int img = i * 64 + sub;           // o*32 + c
        Ks[((img & 31) * 8 + hl) * KSTR + (img >> 5)] =
            h2f(Kf[((size_t)img * WB + wb) * HH + h0 + hl]);
    }
    __syncthreads();

    int bq = tid & 3;
    int q  = (tid >> 2) & 7;
    int op = tid >> 5;
    const float4* X4 = (const float4*)Xs;
    const float4* K4 = (const float4*)Ks;

    float2 acc[4][2];
#pragma unroll
    for (int bi = 0; bi < 4; bi++)
#pragma unroll
        for (int oi = 0; oi < 2; oi++) acc[bi][oi] = make_float2(0.f, 0.f);

#pragma unroll 4
    for (int c = 0; c < 32; c++) {
        int xrow = (c * 8 + q) * (XSTR / 2);
        int krow = (c * 8 + q) * (KSTR / 2);
        float4 xa = X4[xrow + 2 * bq];
        float4 xb = X4[xrow + 2 * bq + 1];
        float4 kv = K4[krow + op];
        float xr[4] = {xa.x, xa.z, xb.x, xb.z};
        float xi[4] = {xa.y, xa.w, xb.y, xb.w};
        float kr[2] = {kv.x, kv.z};
        float ki[2] = {kv.y, kv.w};
#pragma unroll
        for (int bi = 0; bi < 4; bi++)
#pragma unroll
            for (int oi = 0; oi < 2; oi++) {
                acc[bi][oi].x = fmaf(xr[bi], kr[oi], fmaf(-xi[bi], ki[oi], acc[bi][oi].x));
                acc[bi][oi].y = fmaf(xr[bi], ki[oi], fmaf( xi[bi], kr[oi], acc[bi][oi].y));
            }
    }

    int b0 = 4 * bq, o0 = 2 * op, h = h0 + q;
#pragma unroll
    for (int bi = 0; bi < 4; bi++)
#pragma unroll
        for (int oi = 0; oi < 2; oi++)
            Of[(((size_t)(b0 + bi) * NO + o0 + oi) * WB + wb) * HH + h] = f2h(acc[bi][oi]);
}

// ---------------------------------------------------------------------------
extern "C" void kernel_launch(void* const* d_in, const int* in_sizes, int n_in,
                              void* d_out, int out_size) {
    const float* x = (const float*)d_in[0];
    const float* w = (const float*)d_in[1];
    float* out = (float*)d_out;

    __half2 *xf, *kf, *of;
    cudaGetSymbolAddress((void**)&xf, g_Xf);
    cudaGetSymbolAddress((void**)&kf, g_Kf);
    cudaGetSymbolAddress((void**)&of, g_Of);

    const int fwd_smem = 256 * 128 * (int)sizeof(__half2);   // 131072
    const int inv_smem = 129 * 256 * (int)sizeof(__half2);   // 132096
    cudaFuncSetAttribute(fwd_kernel,
                         cudaFuncAttributeMaxDynamicSharedMemorySize, fwd_smem);
    cudaFuncSetAttribute(inv_kernel,
                         cudaFuncAttributeMaxDynamicSharedMemorySize, inv_smem);

    fwd_kernel<<<NB * NC, 1024, fwd_smem>>>(x, xf);
    fwd_kernel<<<NO * NC, 1024, fwd_smem>>>(w, kf);

    size_t bsm = (size_t)(32 * 8 * (XSTR + KSTR)) * sizeof(float2);
    cudaFuncSetAttribute(binconv_kernel,
                         cudaFuncAttributeMaxDynamicSharedMemorySize, (int)bsm);
    binconv_kernel<<<dim3(32, WB), 512, bsm>>>(xf, kf, of);

    inv_kernel<<<NB * NO, 1024, inv_smem>>>(of, out);
}

// round 11
// speedup vs baseline: 1.0097x; 1.0097x over previous
#include <cuda_runtime.h>
#include <cuda_fp16.h>
#include <math_constants.h>

#define NB 16
#define NC 32
#define NO 32
#define HH 256
#define WW 256
#define WB 129

// Frequency-domain scratch in fp16 (half2 = one complex), layout [img][wb][h];
// h is PERMUTED (position k2*32+lane <-> freq 8*br5(lane)+k2).
__device__ __half2 g_Xf[(size_t)NB * NC * WB * HH];
__device__ __half2 g_Kf[(size_t)NO * NC * WB * HH];
__device__ __half2 g_Of[(size_t)NB * NO * WB * HH];

// ---------------------------------------------------------------------------
// Packed complex: one fp32 (re, im) pair in a 64-bit register pair (f32x2).
// ---------------------------------------------------------------------------
typedef unsigned long long cplx;

__device__ __forceinline__ cplx cpk(float x, float y) {
    cplx r; asm("mov.b64 %0, {%1, %2};" : "=l"(r) : "f"(x), "f"(y)); return r;
}
__device__ __forceinline__ float2 cup(cplx a) {
    float2 r; asm("mov.b64 {%0, %1}, %2;" : "=f"(r.x), "=f"(r.y) : "l"(a)); return r;
}
__device__ __forceinline__ cplx cadd2(cplx a, cplx b) {
    cplx r; asm("add.rn.f32x2 %0, %1, %2;" : "=l"(r) : "l"(a), "l"(b)); return r;
}
__device__ __forceinline__ cplx cmul2(cplx a, cplx b) {
    cplx r; asm("mul.rn.f32x2 %0, %1, %2;" : "=l"(r) : "l"(a), "l"(b)); return r;
}
__device__ __forceinline__ cplx cfma2(cplx a, cplx b, cplx c) {
    cplx r; asm("fma.rn.f32x2 %0, %1, %2, %3;" : "=l"(r) : "l"(a), "l"(b), "l"(c)); return r;
}
__device__ __forceinline__ cplx cmulw(cplx a, float2 w) {
    float2 t = cup(a);
    return cfma2(cpk(t.y, t.x), cpk(-w.y, w.y), cmul2(a, cpk(w.x, w.x)));
}
template <int DIR>
__device__ __forceinline__ cplx mulJp(cplx a) {
    float2 t = cup(a);
    return (DIR > 0) ? cpk(t.y, -t.x) : cpk(-t.y, t.x);
}
__device__ __forceinline__ float2 cmulf(float2 a, float2 b) {
    return make_float2(fmaf(a.x, b.x, -a.y * b.y), fmaf(a.x, b.y, a.y * b.x));
}
__device__ __forceinline__ float2 h2f(__half2 h) { return __half22float2(h); }
__device__ __forceinline__ __half2 f2h(float2 f) { return __floats2half2_rn(f.x, f.y); }

// ---------------------------------------------------------------------------
// FFT8 over register slots, e^{-i} for DIR=+1
// ---------------------------------------------------------------------------
template <int DIR>
__device__ __forceinline__ void fft8_slots(cplx v[8]) {
    const cplx N1 = cpk(-1.0f, -1.0f);
    const float ds = (DIR > 0) ? -1.0f : 1.0f;
    const float S = 0.70710678118654752f;
    cplx b0 = cadd2(v[0], v[4]), b1 = cfma2(v[4], N1, v[0]);
    cplx b2 = cadd2(v[2], v[6]), b3 = cfma2(v[6], N1, v[2]);
    cplx b4 = cadd2(v[1], v[5]), b5 = cfma2(v[5], N1, v[1]);
    cplx b6 = cadd2(v[3], v[7]), b7 = cfma2(v[7], N1, v[3]);
    cplx t  = mulJp<DIR>(b3);
    cplx c0 = cadd2(b0, b2), c2 = cfma2(b2, N1, b0);
    cplx c1 = cadd2(b1, t),  c3 = cfma2(t, N1, b1);
    t = mulJp<DIR>(b7);
    cplx c4 = cadd2(b4, b6), c6 = cfma2(b6, N1, b4);
    cplx c5 = cadd2(b5, t),  c7 = cfma2(t, N1, b5);
    const float2 W81 = make_float2(S, ds * S);
    const float2 W83 = make_float2(-S, ds * S);
    v[0] = cadd2(c0, c4); v[4] = cfma2(c4, N1, c0);
    t = cmulw(c5, W81);   v[1] = cadd2(c1, t); v[5] = cfma2(t, N1, c1);
    t = mulJp<DIR>(c6);   v[2] = cadd2(c2, t); v[6] = cfma2(t, N1, c2);
    t = cmulw(c7, W83);   v[3] = cadd2(c3, t); v[7] = cfma2(t, N1, c3);
}

// Forward register/shuffle FFT-256. Input v[j]=x[lane+32*j]. Output: lane
// holds X[8*br5(lane)+k2] in v[k2].
template <int DIR>
__device__ __forceinline__ void fft256(cplx v[8], int lane) {
    const float ds = (DIR > 0) ? -1.0f : 1.0f;
    fft8_slots<DIR>(v);

    float ang = ds * CUDART_PI_F * (float)lane * (1.0f / 128.0f);
    float2 w1; __sincosf(ang, &w1.y, &w1.x);
    float2 w2 = cmulf(w1, w1);
    float2 w3 = cmulf(w2, w1);
    float2 w4 = cmulf(w2, w2);
    float2 w5 = cmulf(w4, w1);
    float2 w6 = cmulf(w3, w3);
    float2 w7 = cmulf(w4, w3);
    v[1] = cmulw(v[1], w1); v[2] = cmulw(v[2], w2); v[3] = cmulw(v[3], w3);
    v[4] = cmulw(v[4], w4); v[5] = cmulw(v[5], w5); v[6] = cmulw(v[6], w6);
    v[7] = cmulw(v[7], w7);

#pragma unroll
    for (int m = 16; m >= 1; m >>= 1) {
        bool up = (lane & m) != 0;
        float s = up ? -1.0f : 1.0f;
        cplx s2 = cpk(s, s);
        cplx wxx, wmy;
        if (m > 1) {
            float a2 = ds * CUDART_PI_F * (float)(lane & (m - 1)) / (float)m;
            float2 w; __sincosf(a2, &w.y, &w.x);
            float2 wo = up ? w : make_float2(1.0f, 0.0f);
            wxx = cpk(wo.x, wo.x);
            wmy = cpk(-wo.y, wo.y);
        }
#pragma unroll
        for (int k = 0; k < 8; k++) {
            float2 t = cup(v[k]);
            float ox = __shfl_xor_sync(0xffffffffu, t.x, m);
            float oy = __shfl_xor_sync(0xffffffffu, t.y, m);
            cplx tt = cfma2(v[k], s2, cpk(ox, oy));
            if (m > 1) {
                float2 u = cup(tt);
                v[k] = cfma2(cpk(u.y, u.x), wmy, cmul2(tt, wxx));
            } else {
                v[k] = tt;
            }
        }
    }
}

// Adjoint (unnormalized inverse) of fft256<1>: permuted in, natural out.
__device__ __forceinline__ void ifft256_adj(cplx v[8], int lane) {
#pragma unroll
    for (int m = 1; m <= 16; m <<= 1) {
        bool up = (lane & m) != 0;
        float s = up ? -1.0f : 1.0f;
        cplx s2 = cpk(s, s);
        if (m > 1) {
            float a2 = CUDART_PI_F * (float)(lane & (m - 1)) / (float)m;
            float2 w; __sincosf(a2, &w.y, &w.x);
            float2 wo = up ? w : make_float2(1.0f, 0.0f);
            cplx wxx = cpk(wo.x, wo.x);
            cplx wmy = cpk(-wo.y, wo.y);
#pragma unroll
            for (int k = 0; k < 8; k++) {
                float2 u = cup(v[k]);
                v[k] = cfma2(cpk(u.y, u.x), wmy, cmul2(v[k], wxx));
            }
        }
#pragma unroll
        for (int k = 0; k < 8; k++) {
            float2 t = cup(v[k]);
            float ox = __shfl_xor_sync(0xffffffffu, t.x, m);
            float oy = __shfl_xor_sync(0xffffffffu, t.y, m);
            v[k] = cfma2(v[k], s2, cpk(ox, oy));
        }
    }
    float ang = CUDART_PI_F * (float)lane * (1.0f / 128.0f);
    float2 w1; __sincosf(ang, &w1.y, &w1.x);
    float2 w2 = cmulf(w1, w1);
    float2 w3 = cmulf(w2, w1);
    float2 w4 = cmulf(w2, w2);
    float2 w5 = cmulf(w4, w1);
    float2 w6 = cmulf(w3, w3);
    float2 w7 = cmulf(w4, w3);
    v[1] = cmulw(v[1], w1); v[2] = cmulw(v[2], w2); v[3] = cmulw(v[3], w3);
    v[4] = cmulw(v[4], w4); v[5] = cmulw(v[5], w5); v[6] = cmulw(v[6], w6);
    v[7] = cmulw(v[7], w7);

    fft8_slots<-1>(v);
}

// ---------------------------------------------------------------------------
// Pass 1: forward real row FFT, 2 rows packed, output transposed [img][wb][h]
// ---------------------------------------------------------------------------
__global__ void __launch_bounds__(256)
rowfft_kernel(const float* __restrict__ in, __half2* __restrict__ outF) {
    __shared__ float2 zbuf[8][264];
    int tid = threadIdx.x, lane = tid & 31, wrp = tid >> 5;
    size_t img = blockIdx.y;
    int row0 = blockIdx.x * 16;

    const float* pa = in + (img * HH + row0 + 2 * wrp) * (size_t)WW;
    const float* pb = pa + WW;
    cplx v[8];
#pragma unroll
    for (int j = 0; j < 8; j++)
        v[j] = cpk(pa[lane + 32 * j], pb[lane + 32 * j]);

    fft256<1>(v, lane);

    int k1 = __brev((unsigned)lane) >> 27;
#pragma unroll
    for (int k2 = 0; k2 < 8; k2++) zbuf[wrp][k1 + 33 * k2] = cup(v[k2]);
    __syncthreads();

    for (int idx = tid; idx < WB * 16; idx += 256) {
        int r = idx & 15, k = idx >> 4;
        int p = r >> 1;
        int km = (256 - k) & 255;
        float2 Z  = zbuf[p][(k  & 7) * 33 + (k  >> 3)];
        float2 Zm = zbuf[p][(km & 7) * 33 + (km >> 3)];
        float2 o;
        if (r & 1) o = make_float2(0.5f * (Z.y + Zm.y), 0.5f * (Zm.x - Z.x));
        else       o = make_float2(0.5f * (Z.x + Zm.x), 0.5f * (Z.y - Zm.y));
        outF[(img * WB + k) * (size_t)HH + row0 + r] = f2h(o);
    }
}

// ---------------------------------------------------------------------------
// Pass 2: forward column FFT over h. Coalesced; stores permuted order.
// ---------------------------------------------------------------------------
__global__ void __launch_bounds__(512)
colfft_fwd_kernel(__half2* __restrict__ F) {
    int gid = blockIdx.x * 16 + (threadIdx.x >> 5);
    int lane = threadIdx.x & 31;
    __half2* p = F + (size_t)gid * HH;

    cplx v[8];
#pragma unroll
    for (int j = 0; j < 8; j++) {
        float2 f = h2f(p[lane + 32 * j]);
        v[j] = cpk(f.x, f.y);
    }

    fft256<1>(v, lane);

#pragma unroll
    for (int k2 = 0; k2 < 8; k2++) p[k2 * 32 + lane] = f2h(cup(v[k2]));
}

// ---------------------------------------------------------------------------
// Pass 3: per-bin channel contraction, 4b x 2o tiling, f32x2 packed MACs.
// ---------------------------------------------------------------------------
#define XSTR 18
#define KSTR 34
__global__ void __launch_bounds__(512, 2)
binconv_kernel(const __half2* __restrict__ Xf, const __half2* __restrict__ Kf,
               __half2* __restrict__ Of) {
    extern __shared__ float2 sm[];
    float2* Xs = sm;
    float2* Ks = sm + 32 * 8 * XSTR;

    int tid = threadIdx.x;
    int wb = blockIdx.y;
    int h0 = blockIdx.x * 8;
    int hl = tid & 7;
    int sub = tid >> 3;

#pragma unroll
    for (int i = 0; i < 8; i++) {
        int img = i * 64 + sub;           // b*32 + c
        Xs[((img & 31) * 8 + hl) * XSTR + (img >> 5)] =
            h2f(Xf[((size_t)img * WB + wb) * HH + h0 + hl]);
    }
#pragma unroll
    for (int i = 0; i < 16; i++) {
        int img = i * 64 + sub;           // o*32 + c
        Ks[((img & 31) * 8 + hl) * KSTR + (img >> 5)] =
            h2f(Kf[((size_t)img * WB + wb) * HH + h0 + hl]);
    }
    __syncthreads();

    int bq = tid & 3;
    int q  = (tid >> 2) & 7;
    int op = tid >> 5;
    const float4* X4 = (const float4*)Xs;
    const float4* K4 = (const float4*)Ks;

    cplx acc[4][2];
#pragma unroll
    for (int bi = 0; bi < 4; bi++)
#pragma unroll
        for (int oi = 0; oi < 2; oi++) acc[bi][oi] = cpk(0.f, 0.f);

#pragma unroll 4
    for (int c = 0; c < 32; c++) {
        int xrow = (c * 8 + q) * (XSTR / 2);
        int krow = (c * 8 + q) * (KSTR / 2);
        float4 xa = X4[xrow + 2 * bq];
        float4 xb = X4[xrow + 2 * bq + 1];
        float4 kv = K4[krow + op];
        // packed complex x[bi] and swapped copies (ALU-pipe movs)
        cplx x[4]  = {cpk(xa.x, xa.y), cpk(xa.z, xa.w),
                      cpk(xb.x, xb.y), cpk(xb.z, xb.w)};
        cplx xs[4] = {cpk(xa.y, xa.x), cpk(xa.w, xa.z),
                      cpk(xb.y, xb.x), cpk(xb.w, xb.z)};
        // k broadcast pairs: kxx = (kr,kr), kmy = (-ki,ki)
        cplx kxx[2] = {cpk(kv.x, kv.x), cpk(kv.z, kv.z)};
        cplx kmy[2] = {cpk(-kv.y, kv.y), cpk(-kv.w, kv.w)};
#pragma unroll
        for (int bi = 0; bi < 4; bi++)
#pragma unroll
            for (int oi = 0; oi < 2; oi++)
                acc[bi][oi] = cfma2(xs[bi], kmy[oi],
                               cfma2(x[bi], kxx[oi], acc[bi][oi]));
    }

    int b0 = 4 * bq, o0 = 2 * op, h = h0 + q;
#pragma unroll
    for (int bi = 0; bi < 4; bi++)
#pragma unroll
        for (int oi = 0; oi < 2; oi++)
            Of[(((size_t)(b0 + bi) * NO + o0 + oi) * WB + wb) * HH + h] =
                f2h(cup(acc[bi][oi]));
}

// ---------------------------------------------------------------------------
// Pass 4+5 fused: inverse 2D rFFT, one CTA per output image.
// ---------------------------------------------------------------------------
__global__ void __launch_bounds__(1024)
inv_kernel(const __half2* __restrict__ OF, float* __restrict__ out) {
    extern __shared__ __half2 St[];   // 129 * 256, addr = wb*256 + (h ^ (wb&31))
    int tid = threadIdx.x, lane = tid & 31, wrp = tid >> 5;
    size_t img = blockIdx.x;

    // Phase 1: inverse column FFTs (coalesced permuted loads)
    for (int it = 0; it < 5; it++) {
        int wb = it * 32 + wrp;
        if (wb <= 128) {
            const __half2* p = OF + (img * WB + wb) * (size_t)HH;
            cplx v[8];
#pragma unroll
            for (int k2 = 0; k2 < 8; k2++) {
                float2 f = h2f(p[k2 * 32 + lane]);
                v[k2] = cpk(f.x, f.y);
            }
            ifft256_adj(v, lane);
            int sw = wb & 31;
#pragma unroll
            for (int j = 0; j < 8; j++)
                St[wb * 256 + ((lane + 32 * j) ^ sw)] = f2h(cup(v[j]));
        }
    }
    __syncthreads();

    // Phase 2: packed inverse row FFTs (rows 2p, 2p+1) + scale
#pragma unroll
    for (int it = 0; it < 4; it++) {
        int pi = it * 32 + wrp;
        int r0 = 2 * pi, r1 = 2 * pi + 1;
        cplx v[8];
#pragma unroll
        for (int j = 0; j < 8; j++) {
            int k = lane + 32 * j;
            float2 r;
            if (k <= 128) {
                int sw = k & 31;
                float2 A  = h2f(St[k * 256 + (r0 ^ sw)]);
                float2 Bv = h2f(St[k * 256 + (r1 ^ sw)]);
                r = make_float2(A.x - Bv.y, A.y + Bv.x);
            } else {
                int km = 256 - k, sw = km & 31;
                float2 A  = h2f(St[km * 256 + (r0 ^ sw)]);
                float2 Bv = h2f(St[km * 256 + (r1 ^ sw)]);
                r = make_float2(A.x + Bv.y, Bv.x - A.y);
            }
            v[j] = cpk(r.x, r.y);
        }

        fft256<-1>(v, lane);

        const float sc = 1.0f / 65536.0f;
        int base = 8 * (__brev((unsigned)lane) >> 27);
        float* oa = out + (img * HH + r0) * (size_t)WW + base;
        float* ob = oa + WW;
        float4* oa4 = (float4*)oa; float4* ob4 = (float4*)ob;
        float2 f[8];
#pragma unroll
        for (int j = 0; j < 8; j++) f[j] = cup(v[j]);
#pragma unroll
        for (int qq = 0; qq < 2; qq++) {
            oa4[qq] = make_float4(f[4*qq].x * sc, f[4*qq+1].x * sc, f[4*qq+2].x * sc, f[4*qq+3].x * sc);
            ob4[qq] = make_float4(f[4*qq].y * sc, f[4*qq+1].y * sc, f[4*qq+2].y * sc, f[4*qq+3].y * sc);
        }
    }
}

// ---------------------------------------------------------------------------
extern "C" void kernel_launch(void* const* d_in, const int* in_sizes, int n_in,
                              void* d_out, int out_size) {
    const float* x = (const float*)d_in[0];
    const float* w = (const float*)d_in[1];
    float* out = (float*)d_out;

    __half2 *xf, *kf, *of;
    cudaGetSymbolAddress((void**)&xf, g_Xf);
    cudaGetSymbolAddress((void**)&kf, g_Kf);
    cudaGetSymbolAddress((void**)&of, g_Of);

    rowfft_kernel<<<dim3(16, NB * NC), 256>>>(x, xf);
    rowfft_kernel<<<dim3(16, NO * NC), 256>>>(w, kf);

    colfft_fwd_kernel<<<(NB * NC * WB) / 16, 512>>>(xf);
    colfft_fwd_kernel<<<(NO * NC * WB) / 16, 512>>>(kf);

    size_t bsm = (size_t)(32 * 8 * (XSTR + KSTR)) * sizeof(float2);
    cudaFuncSetAttribute(binconv_kernel,
                         cudaFuncAttributeMaxDynamicSharedMemorySize, (int)bsm);
    binconv_kernel<<<dim3(32, WB), 512, bsm>>>(xf, kf, of);

    const int inv_smem = 129 * 256 * (int)sizeof(__half2);   // 132096
    cudaFuncSetAttribute(inv_kernel,
                         cudaFuncAttributeMaxDynamicSharedMemorySize, inv_smem);
    inv_kernel<<<NB * NO, 1024, inv_smem>>>(of, out);
}

// round 13
// speedup vs baseline: 1.0127x; 1.0030x over previous
#include <cuda_runtime.h>
#include <cuda_fp16.h>
#include <math_constants.h>

#define NB 16
#define NC 32
#define NO 32
#define HH 256
#define WW 256
#define WB 129

// Frequency-domain scratch in fp16 (half2 = one complex), layout [img][wb][h];
// h is PERMUTED (position k2*32+lane <-> freq 8*br5(lane)+k2).
__device__ __half2 g_Xf[(size_t)NB * NC * WB * HH];
__device__ __half2 g_Kf[(size_t)NO * NC * WB * HH];
__device__ __half2 g_Of[(size_t)NB * NO * WB * HH];

// ---------------------------------------------------------------------------
// Packed complex: one fp32 (re, im) pair in a 64-bit register pair (f32x2).
// ---------------------------------------------------------------------------
typedef unsigned long long cplx;

__device__ __forceinline__ cplx cpk(float x, float y) {
    cplx r; asm("mov.b64 %0, {%1, %2};" : "=l"(r) : "f"(x), "f"(y)); return r;
}
__device__ __forceinline__ float2 cup(cplx a) {
    float2 r; asm("mov.b64 {%0, %1}, %2;" : "=f"(r.x), "=f"(r.y) : "l"(a)); return r;
}
__device__ __forceinline__ cplx cswap(cplx a) {
    float2 t = cup(a); return cpk(t.y, t.x);
}
__device__ __forceinline__ cplx cadd2(cplx a, cplx b) {
    cplx r; asm("add.rn.f32x2 %0, %1, %2;" : "=l"(r) : "l"(a), "l"(b)); return r;
}
__device__ __forceinline__ cplx cmul2(cplx a, cplx b) {
    cplx r; asm("mul.rn.f32x2 %0, %1, %2;" : "=l"(r) : "l"(a), "l"(b)); return r;
}
__device__ __forceinline__ cplx cfma2(cplx a, cplx b, cplx c) {
    cplx r; asm("fma.rn.f32x2 %0, %1, %2, %3;" : "=l"(r) : "l"(a), "l"(b), "l"(c)); return r;
}
__device__ __forceinline__ cplx cmulw(cplx a, float2 w) {
    float2 t = cup(a);
    return cfma2(cpk(t.y, t.x), cpk(-w.y, w.y), cmul2(a, cpk(w.x, w.x)));
}
template <int DIR>
__device__ __forceinline__ cplx mulJp(cplx a) {
    float2 t = cup(a);
    return (DIR > 0) ? cpk(t.y, -t.x) : cpk(-t.y, t.x);
}
__device__ __forceinline__ float2 cmulf(float2 a, float2 b) {
    return make_float2(fmaf(a.x, b.x, -a.y * b.y), fmaf(a.x, b.y, a.y * b.x));
}
__device__ __forceinline__ float2 h2f(__half2 h) { return __half22float2(h); }
__device__ __forceinline__ __half2 f2h(float2 f) { return __floats2half2_rn(f.x, f.y); }

// ---------------------------------------------------------------------------
// FFT8 over register slots, e^{-i} for DIR=+1
// ---------------------------------------------------------------------------
template <int DIR>
__device__ __forceinline__ void fft8_slots(cplx v[8]) {
    const cplx N1 = cpk(-1.0f, -1.0f);
    const float ds = (DIR > 0) ? -1.0f : 1.0f;
    const float S = 0.70710678118654752f;
    cplx b0 = cadd2(v[0], v[4]), b1 = cfma2(v[4], N1, v[0]);
    cplx b2 = cadd2(v[2], v[6]), b3 = cfma2(v[6], N1, v[2]);
    cplx b4 = cadd2(v[1], v[5]), b5 = cfma2(v[5], N1, v[1]);
    cplx b6 = cadd2(v[3], v[7]), b7 = cfma2(v[7], N1, v[3]);
    cplx t  = mulJp<DIR>(b3);
    cplx c0 = cadd2(b0, b2), c2 = cfma2(b2, N1, b0);
    cplx c1 = cadd2(b1, t),  c3 = cfma2(t, N1, b1);
    t = mulJp<DIR>(b7);
    cplx c4 = cadd2(b4, b6), c6 = cfma2(b6, N1, b4);
    cplx c5 = cadd2(b5, t),  c7 = cfma2(t, N1, b5);
    const float2 W81 = make_float2(S, ds * S);
    const float2 W83 = make_float2(-S, ds * S);
    v[0] = cadd2(c0, c4); v[4] = cfma2(c4, N1, c0);
    t = cmulw(c5, W81);   v[1] = cadd2(c1, t); v[5] = cfma2(t, N1, c1);
    t = mulJp<DIR>(c6);   v[2] = cadd2(c2, t); v[6] = cfma2(t, N1, c2);
    t = cmulw(c7, W83);   v[3] = cadd2(c3, t); v[7] = cfma2(t, N1, c3);
}

// Forward register/shuffle FFT-256. Input v[j]=x[lane+32*j]. Output: lane
// holds X[8*br5(lane)+k2] in v[k2].
template <int DIR>
__device__ __forceinline__ void fft256(cplx v[8], int lane) {
    const float ds = (DIR > 0) ? -1.0f : 1.0f;
    fft8_slots<DIR>(v);

    float ang = ds * CUDART_PI_F * (float)lane * (1.0f / 128.0f);
    float2 w1; __sincosf(ang, &w1.y, &w1.x);
    float2 w2 = cmulf(w1, w1);
    float2 w3 = cmulf(w2, w1);
    float2 w4 = cmulf(w2, w2);
    float2 w5 = cmulf(w4, w1);
    float2 w6 = cmulf(w3, w3);
    float2 w7 = cmulf(w4, w3);
    v[1] = cmulw(v[1], w1); v[2] = cmulw(v[2], w2); v[3] = cmulw(v[3], w3);
    v[4] = cmulw(v[4], w4); v[5] = cmulw(v[5], w5); v[6] = cmulw(v[6], w6);
    v[7] = cmulw(v[7], w7);

#pragma unroll
    for (int m = 16; m >= 1; m >>= 1) {
        bool up = (lane & m) != 0;
        float s = up ? -1.0f : 1.0f;
        cplx s2 = cpk(s, s);
        cplx wxx, wmy;
        if (m > 1) {
            float a2 = ds * CUDART_PI_F * (float)(lane & (m - 1)) / (float)m;
            float2 w; __sincosf(a2, &w.y, &w.x);
            float2 wo = up ? w : make_float2(1.0f, 0.0f);
            wxx = cpk(wo.x, wo.x);
            wmy = cpk(-wo.y, wo.y);
        }
#pragma unroll
        for (int k = 0; k < 8; k++) {
            float2 t = cup(v[k]);
            float ox = __shfl_xor_sync(0xffffffffu, t.x, m);
            float oy = __shfl_xor_sync(0xffffffffu, t.y, m);
            cplx tt = cfma2(v[k], s2, cpk(ox, oy));
            if (m > 1) {
                float2 u = cup(tt);
                v[k] = cfma2(cpk(u.y, u.x), wmy, cmul2(tt, wxx));
            } else {
                v[k] = tt;
            }
        }
    }
}

// Adjoint (unnormalized inverse) of fft256<1>: permuted in, natural out.
__device__ __forceinline__ void ifft256_adj(cplx v[8], int lane) {
#pragma unroll
    for (int m = 1; m <= 16; m <<= 1) {
        bool up = (lane & m) != 0;
        float s = up ? -1.0f : 1.0f;
        cplx s2 = cpk(s, s);
        if (m > 1) {
            float a2 = CUDART_PI_F * (float)(lane & (m - 1)) / (float)m;
            float2 w; __sincosf(a2, &w.y, &w.x);
            float2 wo = up ? w : make_float2(1.0f, 0.0f);
            cplx wxx = cpk(wo.x, wo.x);
            cplx wmy = cpk(-wo.y, wo.y);
#pragma unroll
            for (int k = 0; k < 8; k++) {
                float2 u = cup(v[k]);
                v[k] = cfma2(cpk(u.y, u.x), wmy, cmul2(v[k], wxx));
            }
        }
#pragma unroll
        for (int k = 0; k < 8; k++) {
            float2 t = cup(v[k]);
            float ox = __shfl_xor_sync(0xffffffffu, t.x, m);
            float oy = __shfl_xor_sync(0xffffffffu, t.y, m);
            v[k] = cfma2(v[k], s2, cpk(ox, oy));
        }
    }
    float ang = CUDART_PI_F * (float)lane * (1.0f / 128.0f);
    float2 w1; __sincosf(ang, &w1.y, &w1.x);
    float2 w2 = cmulf(w1, w1);
    float2 w3 = cmulf(w2, w1);
    float2 w4 = cmulf(w2, w2);
    float2 w5 = cmulf(w4, w1);
    float2 w6 = cmulf(w3, w3);
    float2 w7 = cmulf(w4, w3);
    v[1] = cmulw(v[1], w1); v[2] = cmulw(v[2], w2); v[3] = cmulw(v[3], w3);
    v[4] = cmulw(v[4], w4); v[5] = cmulw(v[5], w5); v[6] = cmulw(v[6], w6);
    v[7] = cmulw(v[7], w7);

    fft8_slots<-1>(v);
}

// ---------------------------------------------------------------------------
// Pass 1: forward real row FFT, 2 rows packed, output transposed [img][wb][h]
// ---------------------------------------------------------------------------
__global__ void __launch_bounds__(256)
rowfft_kernel(const float* __restrict__ in, __half2* __restrict__ outF) {
    __shared__ float2 zbuf[8][264];
    int tid = threadIdx.x, lane = tid & 31, wrp = tid >> 5;
    size_t img = blockIdx.y;
    int row0 = blockIdx.x * 16;

    const float* pa = in + (img * HH + row0 + 2 * wrp) * (size_t)WW;
    const float* pb = pa + WW;
    cplx v[8];
#pragma unroll
    for (int j = 0; j < 8; j++)
        v[j] = cpk(pa[lane + 32 * j], pb[lane + 32 * j]);

    fft256<1>(v, lane);

    int k1 = __brev((unsigned)lane) >> 27;
#pragma unroll
    for (int k2 = 0; k2 < 8; k2++) zbuf[wrp][k1 + 33 * k2] = cup(v[k2]);
    __syncthreads();

    for (int idx = tid; idx < WB * 16; idx += 256) {
        int r = idx & 15, k = idx >> 4;
        int p = r >> 1;
        int km = (256 - k) & 255;
        float2 Z  = zbuf[p][(k  & 7) * 33 + (k  >> 3)];
        float2 Zm = zbuf[p][(km & 7) * 33 + (km >> 3)];
        float2 o;
        if (r & 1) o = make_float2(0.5f * (Z.y + Zm.y), 0.5f * (Zm.x - Z.x));
        else       o = make_float2(0.5f * (Z.x + Zm.x), 0.5f * (Z.y - Zm.y));
        outF[(img * WB + k) * (size_t)HH + row0 + r] = f2h(o);
    }
}

// ---------------------------------------------------------------------------
// Pass 2: forward column FFT over h. Coalesced; stores permuted order.
// ---------------------------------------------------------------------------
__global__ void __launch_bounds__(512)
colfft_fwd_kernel(__half2* __restrict__ F) {
    int gid = blockIdx.x * 16 + (threadIdx.x >> 5);
    int lane = threadIdx.x & 31;
    __half2* p = F + (size_t)gid * HH;

    cplx v[8];
#pragma unroll
    for (int j = 0; j < 8; j++) {
        float2 f = h2f(p[lane + 32 * j]);
        v[j] = cpk(f.x, f.y);
    }

    fft256<1>(v, lane);

#pragma unroll
    for (int k2 = 0; k2 < 8; k2++) p[k2 * 32 + lane] = f2h(cup(v[k2]));
}

// ---------------------------------------------------------------------------
// Pass 3: per-bin channel contraction, 4b x 2o tiling.
// Packed dual-accumulator scheme: accP += x (.) k ; accQ += x (.) swap(k)
// Epilogue: Or = accP.re - accP.im ; Oi = accQ.re + accQ.im.
// Zero per-c packing except 2 swaps of k (4 MOVs).
// ---------------------------------------------------------------------------
#define XSTR 18
#define KSTR 34
__global__ void __launch_bounds__(512, 2)
binconv_kernel(const __half2* __restrict__ Xf, const __half2* __restrict__ Kf,
               __half2* __restrict__ Of) {
    extern __shared__ float2 sm[];
    float2* Xs = sm;
    float2* Ks = sm + 32 * 8 * XSTR;

    int tid = threadIdx.x;
    int wb = blockIdx.y;
    int h0 = blockIdx.x * 8;
    int hl = tid & 7;
    int sub = tid >> 3;

#pragma unroll
    for (int i = 0; i < 8; i++) {
        int img = i * 64 + sub;           // b*32 + c
        Xs[((img & 31) * 8 + hl) * XSTR + (img >> 5)] =
            h2f(Xf[((size_t)img * WB + wb) * HH + h0 + hl]);
    }
#pragma unroll
    for (int i = 0; i < 16; i++) {
        int img = i * 64 + sub;           // o*32 + c
        Ks[((img & 31) * 8 + hl) * KSTR + (img >> 5)] =
            h2f(Kf[((size_t)img * WB + wb) * HH + h0 + hl]);
    }
    __syncthreads();

    int bq = tid & 3;
    int q  = (tid >> 2) & 7;
    int op = tid >> 5;
    const ulonglong2* Xc = (const ulonglong2*)Xs;   // 2 packed cplx per elem
    const ulonglong2* Kc = (const ulonglong2*)Ks;

    cplx accP[4][2], accQ[4][2];
#pragma unroll
    for (int bi = 0; bi < 4; bi++)
#pragma unroll
        for (int oi = 0; oi < 2; oi++) {
            accP[bi][oi] = cpk(0.f, 0.f);
            accQ[bi][oi] = cpk(0.f, 0.f);
        }

#pragma unroll 4
    for (int c = 0; c < 32; c++) {
        int xrow = (c * 8 + q) * (XSTR / 2);
        int krow = (c * 8 + q) * (KSTR / 2);
        ulonglong2 xa = Xc[xrow + 2 * bq];      // b0,b1 packed
        ulonglong2 xb = Xc[xrow + 2 * bq + 1];  // b2,b3 packed
        ulonglong2 kk = Kc[krow + op];          // o0,o1 packed
        cplx x[4] = {xa.x, xa.y, xb.x, xb.y};
        cplx k0 = kk.x, k1 = kk.y;
        cplx k0s = cswap(k0), k1s = cswap(k1);
#pragma unroll
        for (int bi = 0; bi < 4; bi++) {
            accP[bi][0] = cfma2(x[bi], k0,  accP[bi][0]);
            accQ[bi][0] = cfma2(x[bi], k0s, accQ[bi][0]);
            accP[bi][1] = cfma2(x[bi], k1,  accP[bi][1]);
            accQ[bi][1] = cfma2(x[bi], k1s, accQ[bi][1]);
        }
    }

    int b0 = 4 * bq, o0 = 2 * op, h = h0 + q;
#pragma unroll
    for (int bi = 0; bi < 4; bi++)
#pragma unroll
        for (int oi = 0; oi < 2; oi++) {
            float2 p2 = cup(accP[bi][oi]);
            float2 q2 = cup(accQ[bi][oi]);
            Of[(((size_t)(b0 + bi) * NO + o0 + oi) * WB + wb) * HH + h] =
                f2h(make_float2(p2.x - p2.y, q2.x + q2.y));
        }
}

// ---------------------------------------------------------------------------
// Pass 4+5 fused: inverse 2D rFFT, one CTA per output image.
// ---------------------------------------------------------------------------
__global__ void __launch_bounds__(1024)
inv_kernel(const __half2* __restrict__ OF, float* __restrict__ out) {
    extern __shared__ __half2 St[];   // 129 * 256, addr = wb*256 + (h ^ (wb&31))
    int tid = threadIdx.x, lane = tid & 31, wrp = tid >> 5;
    size_t img = blockIdx.x;

    // Phase 1: inverse column FFTs (coalesced permuted loads)
    for (int it = 0; it < 5; it++) {
        int wb = it * 32 + wrp;
        if (wb <= 128) {
            const __half2* p = OF + (img * WB + wb) * (size_t)HH;
            cplx v[8];
#pragma unroll
            for (int k2 = 0; k2 < 8; k2++) {
                float2 f = h2f(p[k2 * 32 + lane]);
                v[k2] = cpk(f.x, f.y);
            }
            ifft256_adj(v, lane);
            int sw = wb & 31;
#pragma unroll
            for (int j = 0; j < 8; j++)
                St[wb * 256 + ((lane + 32 * j) ^ sw)] = f2h(cup(v[j]));
        }
    }
    __syncthreads();

    // Phase 2: packed inverse row FFTs (rows 2p, 2p+1) + scale
#pragma unroll
    for (int it = 0; it < 4; it++) {
        int pi = it * 32 + wrp;
        int r0 = 2 * pi, r1 = 2 * pi + 1;
        cplx v[8];
#pragma unroll
        for (int j = 0; j < 8; j++) {
            int k = lane + 32 * j;
            float2 r;
            if (k <= 128) {
                int sw = k & 31;
                float2 A  = h2f(St[k * 256 + (r0 ^ sw)]);
                float2 Bv = h2f(St[k * 256 + (r1 ^ sw)]);
                r = make_float2(A.x - Bv.y, A.y + Bv.x);
            } else {
                int km = 256 - k, sw = km & 31;
                float2 A  = h2f(St[km * 256 + (r0 ^ sw)]);
                float2 Bv = h2f(St[km * 256 + (r1 ^ sw)]);
                r = make_float2(A.x + Bv.y, Bv.x - A.y);
            }
            v[j] = cpk(r.x, r.y);
        }

        fft256<-1>(v, lane);

        const float sc = 1.0f / 65536.0f;
        int base = 8 * (__brev((unsigned)lane) >> 27);
        float* oa = out + (img * HH + r0) * (size_t)WW + base;
        float* ob = oa + WW;
        float4* oa4 = (float4*)oa; float4* ob4 = (float4*)ob;
        float2 f[8];
#pragma unroll
        for (int j = 0; j < 8; j++) f[j] = cup(v[j]);
#pragma unroll
        for (int qq = 0; qq < 2; qq++) {
            oa4[qq] = make_float4(f[4*qq].x * sc, f[4*qq+1].x * sc, f[4*qq+2].x * sc, f[4*qq+3].x * sc);
            ob4[qq] = make_float4(f[4*qq].y * sc, f[4*qq+1].y * sc, f[4*qq+2].y * sc, f[4*qq+3].y * sc);
        }
    }
}

// ---------------------------------------------------------------------------
extern "C" void kernel_launch(void* const* d_in, const int* in_sizes, int n_in,
                              void* d_out, int out_size) {
    const float* x = (const float*)d_in[0];
    const float* w = (const float*)d_in[1];
    float* out = (float*)d_out;

    __half2 *xf, *kf, *of;
    cudaGetSymbolAddress((void**)&xf, g_Xf);
    cudaGetSymbolAddress((void**)&kf, g_Kf);
    cudaGetSymbolAddress((void**)&of, g_Of);

    rowfft_kernel<<<dim3(16, NB * NC), 256>>>(x, xf);
    rowfft_kernel<<<dim3(16, NO * NC), 256>>>(w, kf);

    colfft_fwd_kernel<<<(NB * NC * WB) / 16, 512>>>(xf);
    colfft_fwd_kernel<<<(NO * NC * WB) / 16, 512>>>(kf);

    size_t bsm = (size_t)(32 * 8 * (XSTR + KSTR)) * sizeof(float2);
    cudaFuncSetAttribute(binconv_kernel,
                         cudaFuncAttributeMaxDynamicSharedMemorySize, (int)bsm);
    binconv_kernel<<<dim3(32, WB), 512, bsm>>>(xf, kf, of);

    const int inv_smem = 129 * 256 * (int)sizeof(__half2);   // 132096
    cudaFuncSetAttribute(inv_kernel,
                         cudaFuncAttributeMaxDynamicSharedMemorySize, inv_smem);
    inv_kernel<<<NB * NO, 1024, inv_smem>>>(of, out);
}